// round 1
// baseline (speedup 1.0000x reference)
#include <cuda_runtime.h>
#include <cuda_bf16.h>
#include <cstdint>

// ---------------------------------------------------------------------------
// GaussianRasterizer: N=512 gaussians -> 256x256x3 fp32 image.
// Kernel 1: project + cov2d + bbox + bitonic depth sort (1 block, 512 thr).
// Kernel 2: tiled rasterizer, 16x16 px tiles, order-preserving tile cull,
//           per-pixel front-to-back alpha compositing.
// ---------------------------------------------------------------------------

#define NG   512
#define IMG  256
#define TILE 16

struct GS {  // 64 bytes, depth-sorted
    float4 f0;  // mx, my, inv00, inv01
    float4 f1;  // inv11, opac, xmin, xmax
    float4 f2;  // ymin, ymax, cr, cg
    float4 f3;  // cb, pad, pad, pad
};

__device__ GS g_sorted[NG];

__global__ __launch_bounds__(NG)
void gs_preprocess(const float* __restrict__ pos,
                   const float* __restrict__ cov3d,
                   const float* __restrict__ opac,
                   const float* __restrict__ cols,
                   const float* __restrict__ Km,
                   const float* __restrict__ Rm,
                   const float* __restrict__ tv)
{
    __shared__ float4 sg[NG][4];   // 32 KB
    __shared__ float  sz[NG];
    __shared__ int    sidx[NG];

    const int i = threadIdx.x;

    // camera transform
    const float p0 = pos[3*i+0], p1 = pos[3*i+1], p2 = pos[3*i+2];
    const float cam0 = Rm[0]*p0 + Rm[1]*p1 + Rm[2]*p2 + tv[0];
    const float cam1 = Rm[3]*p0 + Rm[4]*p1 + Rm[5]*p2 + tv[1];
    const float cam2 = Rm[6]*p0 + Rm[7]*p1 + Rm[8]*p2 + tv[2];

    const float pr0 = Km[0]*cam0 + Km[1]*cam1 + Km[2]*cam2;
    const float pr1 = Km[3]*cam0 + Km[4]*cam1 + Km[5]*cam2;
    const float pr2 = Km[6]*cam0 + Km[7]*cam1 + Km[8]*cam2;
    const float mx = pr0 / pr2;
    const float my = pr1 / pr2;

    const float z  = cam2;
    const float fx = Km[0], fy = Km[4];
    const float iz = 1.0f / z;
    const float jx0 = fx * iz;
    const float jx2 = -fx * cam0 * iz * iz;
    const float jy1 = fy * iz;
    const float jy2 = -fy * cam1 * iz * iz;

    // cov_cam = R * C * R^T
    float C[9];
    #pragma unroll
    for (int k = 0; k < 9; k++) C[k] = cov3d[9*i + k];

    float M[9];   // M = R*C
    #pragma unroll
    for (int r = 0; r < 3; r++)
        #pragma unroll
        for (int c = 0; c < 3; c++)
            M[3*r+c] = Rm[3*r+0]*C[0*3+c] + Rm[3*r+1]*C[1*3+c] + Rm[3*r+2]*C[2*3+c];

    float CC[9];  // CC = M*R^T
    #pragma unroll
    for (int r = 0; r < 3; r++)
        #pragma unroll
        for (int c = 0; c < 3; c++)
            CC[3*r+c] = M[3*r+0]*Rm[3*c+0] + M[3*r+1]*Rm[3*c+1] + M[3*r+2]*Rm[3*c+2];

    // cov2d = J * CC * J^T + 0.3 I  (Jx = [jx0,0,jx2], Jy = [0,jy1,jy2])
    const float u0 = CC[0]*jx0 + CC[2]*jx2;
    const float u1 = CC[3]*jx0 + CC[5]*jx2;
    const float u2 = CC[6]*jx0 + CC[8]*jx2;
    const float v1 = CC[4]*jy1 + CC[5]*jy2;
    const float v2 = CC[7]*jy1 + CC[8]*jy2;

    const float a = jx0*u0 + jx2*u2 + 0.3f;
    const float b = jy1*u1 + jy2*u2;
    const float c = jy1*v1 + jy2*v2 + 0.3f;

    const float det   = fmaxf(a*c - b*b, 1e-8f);
    const float idet  = 1.0f / det;
    const float inv00 =  c * idet;
    const float inv01 = -b * idet;
    const float inv11 =  a * idet;

    const float half_diff = (a - c) * 0.5f;
    const float max_eig = (a + c)*0.5f + sqrtf(fmaxf(half_diff*half_diff + b*b, 1e-8f));
    const float radius = 3.0f * sqrtf(max_eig);

    const float x_min = fmaxf(0.0f,        truncf(mx - radius));
    const float x_max = fminf((float)IMG,  truncf(mx + radius) + 1.0f);
    const float y_min = fmaxf(0.0f,        truncf(my - radius));
    const float y_max = fminf((float)IMG,  truncf(my + radius) + 1.0f);

    sg[i][0] = make_float4(mx, my, inv00, inv01);
    sg[i][1] = make_float4(inv11, opac[i], x_min, x_max);
    sg[i][2] = make_float4(y_min, y_max, cols[3*i+0], cols[3*i+1]);
    sg[i][3] = make_float4(cols[3*i+2], 0.f, 0.f, 0.f);
    sz[i]   = z;
    sidx[i] = i;

    // bitonic ascending sort on (z, idx) — stable-equivalent to jnp.argsort
    for (int k = 2; k <= NG; k <<= 1) {
        for (int j = k >> 1; j > 0; j >>= 1) {
            __syncthreads();
            const int ixj = i ^ j;
            if (ixj > i) {
                const bool up = ((i & k) == 0);
                const float zi = sz[i], zj = sz[ixj];
                const int   ii = sidx[i], ij = sidx[ixj];
                const bool gt = (zi > zj) || (zi == zj && ii > ij);
                if (gt == up) {
                    sz[i] = zj;  sz[ixj] = zi;
                    sidx[i] = ij; sidx[ixj] = ii;
                }
            }
        }
    }
    __syncthreads();

    const int src = sidx[i];
    g_sorted[i].f0 = sg[src][0];
    g_sorted[i].f1 = sg[src][1];
    g_sorted[i].f2 = sg[src][2];
    g_sorted[i].f3 = sg[src][3];
}

__global__ __launch_bounds__(TILE*TILE)
void gs_raster(float* __restrict__ out)
{
    __shared__ float4 list[NG][4];     // 32 KB, compacted sorted-order list
    __shared__ int warpTotals[8];

    const int tid  = threadIdx.x;
    const int lane = tid & 31;
    const int wid  = tid >> 5;

    const int tileX = blockIdx.x * TILE;
    const int tileY = blockIdx.y * TILE;
    const float px = (float)(tileX + (tid % TILE));
    const float py = (float)(tileY + (tid / TILE));
    const float tX0 = (float)tileX, tX1 = (float)(tileX + TILE);
    const float tY0 = (float)tileY, tY1 = (float)(tileY + TILE);

    int count = 0;
    #pragma unroll
    for (int base = 0; base < NG; base += TILE*TILE) {
        const int g = base + tid;
        const float4 f1 = g_sorted[g].f1;   // xmin(z) xmax(w)
        const float4 f2 = g_sorted[g].f2;   // ymin(x) ymax(y)
        const bool flag = (f1.z < tX1) && (f1.w > tX0) &&
                          (f2.x < tY1) && (f2.y > tY0);

        const unsigned m = __ballot_sync(0xffffffffu, flag);
        if (lane == 0) warpTotals[wid] = __popc(m);
        __syncthreads();

        int offset = count;
        #pragma unroll
        for (int w = 0; w < 8; w++) if (w < wid) offset += warpTotals[w];
        const int pos = offset + __popc(m & ((1u << lane) - 1u));

        if (flag) {
            list[pos][0] = g_sorted[g].f0;
            list[pos][1] = f1;
            list[pos][2] = f2;
            list[pos][3] = g_sorted[g].f3;
        }
        int total = 0;
        #pragma unroll
        for (int w = 0; w < 8; w++) total += warpTotals[w];
        count += total;
        __syncthreads();
    }

    // front-to-back compositing over the tile's sorted list
    float T = 1.0f, r = 0.0f, gch = 0.0f, bch = 0.0f;
    for (int k = 0; k < count; k++) {
        const float4 f0 = list[k][0];
        const float4 f1 = list[k][1];
        const float4 f2 = list[k][2];
        if (px >= f1.z && px < f1.w && py >= f2.x && py < f2.y) {
            const float dx = px - f0.x;
            const float dy = py - f0.y;
            const float mahal = f0.z*dx*dx + 2.0f*f0.w*dx*dy + f1.x*dy*dy;
            const float alpha = f1.y * __expf(-0.5f * mahal);
            const float w = alpha * T;
            const float cb = list[k][3].x;
            r   += w * f2.z;
            gch += w * f2.w;
            bch += w * cb;
            T *= (1.0f - alpha);
            if (T < 1e-5f) break;   // remaining contribution bounded by 1e-5 abs
        }
    }

    const int pyi = tileY + tid / TILE;
    const int pxi = tileX + tid % TILE;
    const int idx = (pyi * IMG + pxi) * 3;
    out[idx + 0] = r;
    out[idx + 1] = gch;
    out[idx + 2] = bch;
}

extern "C" void kernel_launch(void* const* d_in, const int* in_sizes, int n_in,
                              void* d_out, int out_size)
{
    const float* pos   = (const float*)d_in[0];  // (512,3)
    const float* cov3d = (const float*)d_in[1];  // (512,3,3)
    const float* opac  = (const float*)d_in[2];  // (512,1)
    const float* cols  = (const float*)d_in[3];  // (512,3)
    const float* Km    = (const float*)d_in[4];  // (3,3)
    const float* Rm    = (const float*)d_in[5];  // (3,3)
    const float* tv    = (const float*)d_in[6];  // (3,)
    float* out = (float*)d_out;                  // (256,256,3)

    gs_preprocess<<<1, NG>>>(pos, cov3d, opac, cols, Km, Rm, tv);
    gs_raster<<<dim3(IMG/TILE, IMG/TILE), TILE*TILE>>>(out);
}

// round 2
// speedup vs baseline: 1.0970x; 1.0970x over previous
#include <cuda_runtime.h>
#include <cuda_bf16.h>
#include <cstdint>

// ---------------------------------------------------------------------------
// Fused Gaussian rasterizer: each block redundantly projects all 512
// gaussians (1/thread, registers only), culls to its 32x16 tile, sorts the
// ~40 survivors by depth (packed u64 bitonic), composites front-to-back.
// Single launch, single wave (128 blocks < 148 SMs).
// ---------------------------------------------------------------------------

#define NG    512
#define IMG   256
#define TW    32      // tile width  (px)
#define TH    16      // tile height (px)
#define NT    512     // threads per block
#define NWARP (NT/32)

__global__ __launch_bounds__(NT)
void gs_fused(const float* __restrict__ pos,
              const float* __restrict__ cov3d,
              const float* __restrict__ opac,
              const float* __restrict__ cols,
              const float* __restrict__ Km,
              const float* __restrict__ Rm,
              const float* __restrict__ tv,
              float* __restrict__ out)
{
    __shared__ float4             list[NG][4];   // 32 KB compacted records
    __shared__ unsigned long long skey[NG];      // 4 KB sort keys
    __shared__ short              sorder[NG];    // 1 KB sorted indices
    __shared__ int                warpTotals[NWARP];

    const int tid  = threadIdx.x;
    const int lane = tid & 31;
    const int wid  = tid >> 5;

    const int tileX = blockIdx.x * TW;
    const int tileY = blockIdx.y * TH;
    const float tX0 = (float)tileX, tX1 = (float)(tileX + TW);
    const float tY0 = (float)tileY, tY1 = (float)(tileY + TH);

    // ---- phase 1: project gaussian g = tid (registers only) ----
    const int g = tid;
    const float p0 = pos[3*g+0], p1 = pos[3*g+1], p2 = pos[3*g+2];
    const float r0 = Rm[0], r1 = Rm[1], r2 = Rm[2];
    const float r3 = Rm[3], r4 = Rm[4], r5 = Rm[5];
    const float r6 = Rm[6], r7 = Rm[7], r8 = Rm[8];

    const float cam0 = r0*p0 + r1*p1 + r2*p2 + tv[0];
    const float cam1 = r3*p0 + r4*p1 + r5*p2 + tv[1];
    const float cam2 = r6*p0 + r7*p1 + r8*p2 + tv[2];

    const float pr0 = Km[0]*cam0 + Km[1]*cam1 + Km[2]*cam2;
    const float pr1 = Km[3]*cam0 + Km[4]*cam1 + Km[5]*cam2;
    const float pr2 = Km[6]*cam0 + Km[7]*cam1 + Km[8]*cam2;
    const float mx = pr0 / pr2;
    const float my = pr1 / pr2;

    const float z  = cam2;
    const float fx = Km[0], fy = Km[4];
    const float iz  = 1.0f / z;
    const float jx0 = fx * iz;
    const float jx2 = -fx * cam0 * iz * iz;
    const float jy1 = fy * iz;
    const float jy2 = -fy * cam1 * iz * iz;

    float C[9];
    #pragma unroll
    for (int k = 0; k < 9; k++) C[k] = cov3d[9*g + k];

    float M_[9];   // R * C
    #pragma unroll
    for (int r = 0; r < 3; r++) {
        const float a0 = Rm[3*r+0], a1 = Rm[3*r+1], a2 = Rm[3*r+2];
        #pragma unroll
        for (int c = 0; c < 3; c++)
            M_[3*r+c] = a0*C[0*3+c] + a1*C[1*3+c] + a2*C[2*3+c];
    }
    float CC[9];  // (R*C) * R^T
    #pragma unroll
    for (int r = 0; r < 3; r++)
        #pragma unroll
        for (int c = 0; c < 3; c++)
            CC[3*r+c] = M_[3*r+0]*Rm[3*c+0] + M_[3*r+1]*Rm[3*c+1] + M_[3*r+2]*Rm[3*c+2];

    const float u0 = CC[0]*jx0 + CC[2]*jx2;
    const float u1 = CC[3]*jx0 + CC[5]*jx2;
    const float u2 = CC[6]*jx0 + CC[8]*jx2;
    const float v1 = CC[4]*jy1 + CC[5]*jy2;
    const float v2 = CC[7]*jy1 + CC[8]*jy2;

    const float a = jx0*u0 + jx2*u2 + 0.3f;
    const float b = jy1*u1 + jy2*u2;
    const float c = jy1*v1 + jy2*v2 + 0.3f;

    const float det   = fmaxf(a*c - b*b, 1e-8f);
    const float idet  = 1.0f / det;
    const float inv00 =  c * idet;
    const float inv01 = -b * idet;
    const float inv11 =  a * idet;

    const float hd = (a - c) * 0.5f;
    const float max_eig = (a + c)*0.5f + sqrtf(fmaxf(hd*hd + b*b, 1e-8f));
    const float radius = 3.0f * sqrtf(max_eig);

    const float x_min = fmaxf(0.0f,       truncf(mx - radius));
    const float x_max = fminf((float)IMG, truncf(mx + radius) + 1.0f);
    const float y_min = fmaxf(0.0f,       truncf(my - radius));
    const float y_max = fminf((float)IMG, truncf(my + radius) + 1.0f);

    // ---- phase 2: tile cull + order-preserving compaction ----
    const bool flag = (x_min < tX1) && (x_max > tX0) &&
                      (y_min < tY1) && (y_max > tY0);

    const unsigned m = __ballot_sync(0xffffffffu, flag);
    if (lane == 0) warpTotals[wid] = __popc(m);
    __syncthreads();

    int offset = 0, count = 0;
    #pragma unroll
    for (int w = 0; w < NWARP; w++) {
        const int t = warpTotals[w];
        if (w < wid) offset += t;
        count += t;
    }
    const int pos_ = offset + __popc(m & ((1u << lane) - 1u));

    if (flag) {
        list[pos_][0] = make_float4(mx, my, inv00, inv01);
        list[pos_][1] = make_float4(inv11, opac[g], cols[3*g+0], cols[3*g+1]);
        list[pos_][2] = make_float4(x_min, x_max, y_min, y_max);
        list[pos_][3] = make_float4(cols[3*g+2], 0.f, 0.f, 0.f);
        // key: z-bits (32) | orig idx (9) | compact pos (9) -> stable depth sort
        skey[pos_] = ((unsigned long long)__float_as_uint(z) << 18)
                   | ((unsigned long long)g << 9)
                   | (unsigned long long)pos_;
    }

    // pad to next pow2 with +inf keys
    int Mp = 1;
    while (Mp < count) Mp <<= 1;
    if (tid >= count && tid < Mp) skey[tid] = ~0ull;
    __syncthreads();

    // ---- phase 3: bitonic sort of survivor keys (ascending) ----
    for (int k = 2; k <= Mp; k <<= 1) {
        for (int j = k >> 1; j > 0; j >>= 1) {
            const int ixj = tid ^ j;
            if (tid < Mp && ixj > tid) {
                const unsigned long long ki = skey[tid], kj = skey[ixj];
                const bool up = ((tid & k) == 0);
                if ((ki > kj) == up) { skey[tid] = kj; skey[ixj] = ki; }
            }
            __syncthreads();
        }
    }
    if (tid < count) sorder[tid] = (short)(skey[tid] & 0x1FFu);
    __syncthreads();

    // ---- phase 4: per-pixel front-to-back compositing ----
    const int pxi = tileX + (tid & (TW - 1));
    const int pyi = tileY + (tid >> 5);
    const float px = (float)pxi;
    const float py = (float)pyi;

    float T = 1.0f, rr = 0.0f, gg = 0.0f, bb = 0.0f;
    for (int k = 0; k < count; k++) {
        const int gi = sorder[k];
        const float4 f2 = list[gi][2];
        if (px >= f2.x && px < f2.y && py >= f2.z && py < f2.w) {
            const float4 f0 = list[gi][0];
            const float4 f1 = list[gi][1];
            const float dx = px - f0.x;
            const float dy = py - f0.y;
            const float mahal = f0.z*dx*dx + 2.0f*f0.w*dx*dy + f1.x*dy*dy;
            const float alpha = f1.y * __expf(-0.5f * mahal);
            const float w = alpha * T;
            const float cb = list[gi][3].x;
            rr += w * f1.z;
            gg += w * f1.w;
            bb += w * cb;
            T *= (1.0f - alpha);
            if (T < 1e-5f) break;
        }
    }

    const int idx = (pyi * IMG + pxi) * 3;
    out[idx + 0] = rr;
    out[idx + 1] = gg;
    out[idx + 2] = bb;
}

extern "C" void kernel_launch(void* const* d_in, const int* in_sizes, int n_in,
                              void* d_out, int out_size)
{
    const float* pos   = (const float*)d_in[0];  // (512,3)
    const float* cov3d = (const float*)d_in[1];  // (512,3,3)
    const float* opac  = (const float*)d_in[2];  // (512,1)
    const float* cols  = (const float*)d_in[3];  // (512,3)
    const float* Km    = (const float*)d_in[4];  // (3,3)
    const float* Rm    = (const float*)d_in[5];  // (3,3)
    const float* tv    = (const float*)d_in[6];  // (3,)
    float* out = (float*)d_out;                  // (256,256,3)

    gs_fused<<<dim3(IMG/TW, IMG/TH), NT>>>(pos, cov3d, opac, cols, Km, Rm, tv, out);
}

// round 4
// speedup vs baseline: 1.2239x; 1.1157x over previous
#include <cuda_runtime.h>
#include <cuda_bf16.h>
#include <cstdint>

// ---------------------------------------------------------------------------
// Fused Gaussian rasterizer, R3 (resubmit after infra failure):
//  - per-block redundant projection (lean symmetric P·C·P^T form)
//  - ballot compaction to tile list
//  - rank-counting depth sort (2 barriers, no bitonic)
//  - per-pixel front-to-back compositing with exp2-prescaled quadratic
// 128 blocks (32x16 px tiles) x 512 threads = single wave on 148 SMs.
// ---------------------------------------------------------------------------

#define NG    512
#define IMG   256
#define TW    32
#define TH    16
#define NT    512
#define NWARP (NT/32)

__global__ __launch_bounds__(NT)
void gs_fused(const float* __restrict__ pos,
              const float* __restrict__ cov3d,
              const float* __restrict__ opac,
              const float* __restrict__ cols,
              const float* __restrict__ Km,
              const float* __restrict__ Rm,
              const float* __restrict__ tv,
              float* __restrict__ out)
{
    __shared__ float4             list[NG][4];   // 32 KB
    __shared__ unsigned long long skey[NG];      // 4 KB
    __shared__ short              sorder[NG];    // 1 KB
    __shared__ int                warpTotals[NWARP];

    const int tid  = threadIdx.x;
    const int lane = tid & 31;
    const int wid  = tid >> 5;

    const int tileX = blockIdx.x * TW;
    const int tileY = blockIdx.y * TH;
    const float tX0 = (float)tileX, tX1 = (float)(tileX + TW);
    const float tY0 = (float)tileY, tY1 = (float)(tileY + TH);

    // ---------------- phase 1: project gaussian g = tid ----------------
    const int g = tid;
    const float p0 = pos[3*g+0], p1 = pos[3*g+1], p2 = pos[3*g+2];

    const float r00 = Rm[0], r01 = Rm[1], r02 = Rm[2];
    const float r10 = Rm[3], r11 = Rm[4], r12 = Rm[5];
    const float r20 = Rm[6], r21 = Rm[7], r22 = Rm[8];

    const float cam0 = r00*p0 + r01*p1 + r02*p2 + tv[0];
    const float cam1 = r10*p0 + r11*p1 + r12*p2 + tv[1];
    const float cam2 = r20*p0 + r21*p1 + r22*p2 + tv[2];

    const float pr0 = Km[0]*cam0 + Km[1]*cam1 + Km[2]*cam2;
    const float pr1 = Km[3]*cam0 + Km[4]*cam1 + Km[5]*cam2;
    const float pr2 = Km[6]*cam0 + Km[7]*cam1 + Km[8]*cam2;
    const float mx = pr0 / pr2;
    const float my = pr1 / pr2;

    const float z   = cam2;
    const float fx  = Km[0], fy = Km[4];
    const float iz  = 1.0f / z;
    const float jx0 = fx * iz;
    const float jx2 = -fx * cam0 * iz * iz;
    const float jy1 = fy * iz;
    const float jy2 = -fy * cam1 * iz * iz;

    // P = J * R  (2x3)
    const float P00 = jx0*r00 + jx2*r20;
    const float P01 = jx0*r01 + jx2*r21;
    const float P02 = jx0*r02 + jx2*r22;
    const float P10 = jy1*r10 + jy2*r20;
    const float P11 = jy1*r11 + jy2*r21;
    const float P12 = jy1*r12 + jy2*r22;

    // symmetric C (cov3d = A A^T + eps I)
    const float c00 = cov3d[9*g+0];
    const float c01 = cov3d[9*g+1];
    const float c02 = cov3d[9*g+2];
    const float c11 = cov3d[9*g+4];
    const float c12 = cov3d[9*g+5];
    const float c22 = cov3d[9*g+8];

    // t0 = C * P0^T ; t1 = C * P1^T
    const float t00 = c00*P00 + c01*P01 + c02*P02;
    const float t01 = c01*P00 + c11*P01 + c12*P02;
    const float t02 = c02*P00 + c12*P01 + c22*P02;
    const float t10 = c00*P10 + c01*P11 + c02*P12;
    const float t11 = c01*P10 + c11*P11 + c12*P12;
    const float t12 = c02*P10 + c12*P11 + c22*P12;

    const float a = P00*t00 + P01*t01 + P02*t02 + 0.3f;
    const float b = P10*t00 + P11*t01 + P12*t02;
    const float c = P10*t10 + P11*t11 + P12*t12 + 0.3f;

    const float det  = fmaxf(a*c - b*b, 1e-8f);
    const float idet = 1.0f / det;
    // exp2-prescaled inverse covariance:
    //   exp(-0.5*m) = exp2(-0.72134752*m)   (log2(e)*0.5)
    const float e00 = -0.72134752f * c * idet;
    const float e01 =  1.44269504f * b * idet;   // (-log2e)*2*(-b/det)
    const float e11 = -0.72134752f * a * idet;

    const float hd = (a - c) * 0.5f;
    const float max_eig = (a + c)*0.5f + sqrtf(fmaxf(hd*hd + b*b, 1e-8f));
    const float radius = 3.0f * sqrtf(max_eig);

    const float x_min = fmaxf(0.0f,       truncf(mx - radius));
    const float x_max = fminf((float)IMG, truncf(mx + radius) + 1.0f);
    const float y_min = fmaxf(0.0f,       truncf(my - radius));
    const float y_max = fminf((float)IMG, truncf(my + radius) + 1.0f);

    // ---------------- phase 2: tile cull + compaction ----------------
    const bool flag = (x_min < tX1) && (x_max > tX0) &&
                      (y_min < tY1) && (y_max > tY0);

    const unsigned m = __ballot_sync(0xffffffffu, flag);
    if (lane == 0) warpTotals[wid] = __popc(m);
    __syncthreads();

    int offset = 0, count = 0;
    #pragma unroll
    for (int w = 0; w < NWARP; w++) {
        const int t = warpTotals[w];
        if (w < wid) offset += t;
        count += t;
    }
    const int pos_ = offset + __popc(m & ((1u << lane) - 1u));

    if (flag) {
        list[pos_][0] = make_float4(mx, my, e00, e01);
        list[pos_][1] = make_float4(e11, opac[g], cols[3*g+0], cols[3*g+1]);
        list[pos_][2] = make_float4(x_min, x_max, y_min, y_max);
        list[pos_][3] = make_float4(cols[3*g+2], 0.f, 0.f, 0.f);
        // unique key: z bits (positive float -> monotone uint) | orig index
        skey[pos_] = ((unsigned long long)__float_as_uint(z) << 16)
                   | (unsigned long long)g;
    }
    __syncthreads();

    // ---------------- phase 3: rank-counting sort ----------------
    if (tid < count) {
        const unsigned long long me = skey[tid];
        int rank = 0;
        for (int j = 0; j < count; j++)
            rank += (skey[j] < me);
        sorder[rank] = (short)tid;
    }
    __syncthreads();

    // ---------------- phase 4: composite ----------------
    const int pxi = tileX + (tid & (TW - 1));
    const int pyi = tileY + (tid >> 5);
    const float px = (float)pxi;
    const float py = (float)pyi;

    float T = 1.0f, rr = 0.0f, gg = 0.0f, bb = 0.0f;
    for (int k = 0; k < count; k++) {
        const int gi = sorder[k];
        const float4 f2 = list[gi][2];
        if (px >= f2.x && px < f2.y && py >= f2.z && py < f2.w) {
            const float4 f0 = list[gi][0];
            const float4 f1 = list[gi][1];
            const float dx = px - f0.x;
            const float dy = py - f0.y;
            const float e  = (f0.z*dx + f0.w*dy)*dx + f1.x*dy*dy;
            const float alpha = f1.y * exp2f(e);
            const float w = alpha * T;
            const float cb = list[gi][3].x;
            rr += w * f1.z;
            gg += w * f1.w;
            bb += w * cb;
            T *= (1.0f - alpha);
            if (T < 1e-5f) break;
        }
    }

    const int idx = (pyi * IMG + pxi) * 3;
    out[idx + 0] = rr;
    out[idx + 1] = gg;
    out[idx + 2] = bb;
}

extern "C" void kernel_launch(void* const* d_in, const int* in_sizes, int n_in,
                              void* d_out, int out_size)
{
    const float* pos   = (const float*)d_in[0];  // (512,3)
    const float* cov3d = (const float*)d_in[1];  // (512,3,3)
    const float* opac  = (const float*)d_in[2];  // (512,1)
    const float* cols  = (const float*)d_in[3];  // (512,3)
    const float* Km    = (const float*)d_in[4];  // (3,3)
    const float* Rm    = (const float*)d_in[5];  // (3,3)
    const float* tv    = (const float*)d_in[6];  // (3,)
    float* out = (float*)d_out;                  // (256,256,3)

    gs_fused<<<dim3(IMG/TW, IMG/TH), NT>>>(pos, cov3d, opac, cols, Km, Rm, tv, out);
}

// round 5
// speedup vs baseline: 1.6359x; 1.3367x over previous
#include <cuda_runtime.h>
#include <cuda_bf16.h>
#include <cstdint>

// ---------------------------------------------------------------------------
// Fused Gaussian rasterizer, R5:
//  - per-block redundant projection (symmetric P·C·P^T)
//  - rank-scatter: flagged threads write register records straight into
//    depth-sorted order (no index indirection in the hot loop)
//  - composite loop batched x4: independent poly+EX2 front, tiny serial tail
//  - 3x float4 records, u16-packed bbox, opacity-premultiplied colors
// 128 blocks (32x16 tiles) x 512 threads, single wave.
// ---------------------------------------------------------------------------

#define NG    512
#define IMG   256
#define TW    32
#define TH    16
#define NT    512
#define NWARP (NT/32)

__device__ __forceinline__ float ex2(float x) {
    float y;
    asm("ex2.approx.ftz.f32 %0, %1;" : "=f"(y) : "f"(x));
    return y;
}

__global__ __launch_bounds__(NT)
void gs_fused(const float* __restrict__ pos,
              const float* __restrict__ cov3d,
              const float* __restrict__ opac,
              const float* __restrict__ cols,
              const float* __restrict__ Km,
              const float* __restrict__ Rm,
              const float* __restrict__ tv,
              float* __restrict__ out)
{
    __shared__ float4             rec[NG][3];    // 24 KB depth-ordered records
    __shared__ unsigned long long skey[NG];      // 4 KB
    __shared__ int                warpTotals[NWARP];

    const int tid  = threadIdx.x;
    const int lane = tid & 31;
    const int wid  = tid >> 5;

    const int tileX = blockIdx.x * TW;
    const int tileY = blockIdx.y * TH;
    const float tX0 = (float)tileX, tX1 = (float)(tileX + TW);
    const float tY0 = (float)tileY, tY1 = (float)(tileY + TH);

    // ---------------- phase 1: project gaussian g = tid ----------------
    const int g = tid;
    const float p0 = pos[3*g+0], p1 = pos[3*g+1], p2 = pos[3*g+2];

    const float r00 = Rm[0], r01 = Rm[1], r02 = Rm[2];
    const float r10 = Rm[3], r11 = Rm[4], r12 = Rm[5];
    const float r20 = Rm[6], r21 = Rm[7], r22 = Rm[8];

    const float cam0 = r00*p0 + r01*p1 + r02*p2 + tv[0];
    const float cam1 = r10*p0 + r11*p1 + r12*p2 + tv[1];
    const float cam2 = r20*p0 + r21*p1 + r22*p2 + tv[2];

    const float pr0 = Km[0]*cam0 + Km[1]*cam1 + Km[2]*cam2;
    const float pr1 = Km[3]*cam0 + Km[4]*cam1 + Km[5]*cam2;
    const float pr2 = Km[6]*cam0 + Km[7]*cam1 + Km[8]*cam2;
    const float mx = pr0 / pr2;
    const float my = pr1 / pr2;

    const float z   = cam2;
    const float fx  = Km[0], fy = Km[4];
    const float iz  = 1.0f / z;
    const float jx0 = fx * iz;
    const float jx2 = -fx * cam0 * iz * iz;
    const float jy1 = fy * iz;
    const float jy2 = -fy * cam1 * iz * iz;

    // P = J * R  (2x3)
    const float P00 = jx0*r00 + jx2*r20;
    const float P01 = jx0*r01 + jx2*r21;
    const float P02 = jx0*r02 + jx2*r22;
    const float P10 = jy1*r10 + jy2*r20;
    const float P11 = jy1*r11 + jy2*r21;
    const float P12 = jy1*r12 + jy2*r22;

    // symmetric C
    const float c00 = cov3d[9*g+0];
    const float c01 = cov3d[9*g+1];
    const float c02 = cov3d[9*g+2];
    const float c11 = cov3d[9*g+4];
    const float c12 = cov3d[9*g+5];
    const float c22 = cov3d[9*g+8];

    const float t00 = c00*P00 + c01*P01 + c02*P02;
    const float t01 = c01*P00 + c11*P01 + c12*P02;
    const float t02 = c02*P00 + c12*P01 + c22*P02;
    const float t10 = c00*P10 + c01*P11 + c02*P12;
    const float t11 = c01*P10 + c11*P11 + c12*P12;
    const float t12 = c02*P10 + c12*P11 + c22*P12;

    const float a = P00*t00 + P01*t01 + P02*t02 + 0.3f;
    const float b = P10*t00 + P11*t01 + P12*t02;
    const float c = P10*t10 + P11*t11 + P12*t12 + 0.3f;

    const float det  = fmaxf(a*c - b*b, 1e-8f);
    const float idet = 1.0f / det;
    // exp2 prescale: exp(-0.5*m) = exp2(-0.72134752*m)
    const float e00 = -0.72134752f * c * idet;
    const float e01 =  1.44269504f * b * idet;
    const float e11 = -0.72134752f * a * idet;

    const float hd = (a - c) * 0.5f;
    const float max_eig = (a + c)*0.5f + sqrtf(fmaxf(hd*hd + b*b, 1e-8f));
    const float radius = 3.0f * sqrtf(max_eig);

    const float x_min = fmaxf(0.0f,       truncf(mx - radius));
    const float x_max = fminf((float)IMG, truncf(mx + radius) + 1.0f);
    const float y_min = fmaxf(0.0f,       truncf(my - radius));
    const float y_max = fminf((float)IMG, truncf(my + radius) + 1.0f);

    // ---------------- phase 2: cull + key placement ----------------
    const bool flag = (x_min < tX1) && (x_max > tX0) &&
                      (y_min < tY1) && (y_max > tY0);

    const unsigned m = __ballot_sync(0xffffffffu, flag);
    if (lane == 0) warpTotals[wid] = __popc(m);
    __syncthreads();

    int offset = 0, count = 0;
    #pragma unroll
    for (int w = 0; w < NWARP; w++) {
        const int t = warpTotals[w];
        if (w < wid) offset += t;
        count += t;
    }
    const int pos_ = offset + __popc(m & ((1u << lane) - 1u));

    const unsigned long long mykey =
        ((unsigned long long)__float_as_uint(z) << 16) | (unsigned long long)g;
    if (flag) skey[pos_] = mykey;
    __syncthreads();

    // ---------------- phase 3: rank + direct scatter of register record ----
    if (flag) {
        int rank = 0;
        for (int j = 0; j < count; j++)
            rank += (skey[j] < mykey);

        const float op  = opac[g];
        const float ocr = op * cols[3*g+0];
        const float ocg = op * cols[3*g+1];
        const float ocb = op * cols[3*g+2];
        const unsigned lo = (unsigned)x_min | ((unsigned)x_max << 16);
        const unsigned hi = (unsigned)y_min | ((unsigned)y_max << 16);

        rec[rank][0] = make_float4(mx, my, e00, e01);
        rec[rank][1] = make_float4(e11, ocr, ocg, ocb);
        rec[rank][2] = make_float4(op, __uint_as_float(lo), __uint_as_float(hi), 0.f);
    }
    // pad to multiple of 4 with empty-bbox dummies
    const int countPad = (count + 3) & ~3;
    if (tid >= count && tid < countPad) {
        rec[tid][0] = make_float4(0.f, 0.f, 0.f, 0.f);
        rec[tid][1] = make_float4(0.f, 0.f, 0.f, 0.f);
        const unsigned lo = 256u;          // x0=256, x1=0 -> never inside
        rec[tid][2] = make_float4(0.f, __uint_as_float(lo), __uint_as_float(lo), 0.f);
    }
    __syncthreads();

    // ---------------- phase 4: batched composite ----------------
    const int pxi = tileX + (tid & (TW - 1));
    const int pyi = tileY + (tid >> 5);
    const float pxf = (float)pxi;
    const float pyf = (float)pyi;

    float T = 1.0f, rr = 0.0f, gg = 0.0f, bb = 0.0f;
    for (int base = 0; base < countPad; base += 4) {
        float4 q0[4], q1[4], q2[4];
        #pragma unroll
        for (int i = 0; i < 4; i++) {
            q0[i] = rec[base+i][0];
            q1[i] = rec[base+i][1];
            q2[i] = rec[base+i][2];
        }
        float gs[4];
        #pragma unroll
        for (int i = 0; i < 4; i++) {
            const unsigned lo = __float_as_uint(q2[i].y);
            const unsigned hi = __float_as_uint(q2[i].z);
            const int x0 = (int)(lo & 0xffffu), x1 = (int)(lo >> 16);
            const int y0 = (int)(hi & 0xffffu), y1 = (int)(hi >> 16);
            const bool inb = (pxi >= x0) & (pxi < x1) & (pyi >= y0) & (pyi < y1);
            const float dx = pxf - q0[i].x;
            const float dy = pyf - q0[i].y;
            const float e  = fmaf(fmaf(q0[i].w, dy, q0[i].z*dx), dx, q1[i].x*dy*dy);
            gs[i] = inb ? ex2(e) : 0.0f;
        }
        #pragma unroll
        for (int i = 0; i < 4; i++) {
            const float tg = T * gs[i];
            rr = fmaf(tg, q1[i].y, rr);
            gg = fmaf(tg, q1[i].z, gg);
            bb = fmaf(tg, q1[i].w, bb);
            T  = fmaf(-tg, q2[i].x, T);
        }
        if (T < 1e-5f) break;
    }

    const int idx = (pyi * IMG + pxi) * 3;
    out[idx + 0] = rr;
    out[idx + 1] = gg;
    out[idx + 2] = bb;
}

extern "C" void kernel_launch(void* const* d_in, const int* in_sizes, int n_in,
                              void* d_out, int out_size)
{
    const float* pos   = (const float*)d_in[0];  // (512,3)
    const float* cov3d = (const float*)d_in[1];  // (512,3,3)
    const float* opac  = (const float*)d_in[2];  // (512,1)
    const float* cols  = (const float*)d_in[3];  // (512,3)
    const float* Km    = (const float*)d_in[4];  // (3,3)
    const float* Rm    = (const float*)d_in[5];  // (3,3)
    const float* tv    = (const float*)d_in[6];  // (3,)
    float* out = (float*)d_out;                  // (256,256,3)

    gs_fused<<<dim3(IMG/TW, IMG/TH), NT>>>(pos, cov3d, opac, cols, Km, Rm, tv, out);
}

// round 6
// speedup vs baseline: 1.9582x; 1.1970x over previous
#include <cuda_runtime.h>
#include <cuda_bf16.h>
#include <cstdint>

// ---------------------------------------------------------------------------
// Fused Gaussian rasterizer, R6:
//  - 16x16 px tiles, 256 CTAs x 256 threads (2 gaussians/thread projection)
//    -> smaller per-tile lists + CTA-level load balancing (occ_lim ~4/SM)
//  - opacity folded into exp2 bias: alpha = exp2(quad + log2(op))
//  - rank-scatter into depth order, batch-4 composite with pipelined EX2
// ---------------------------------------------------------------------------

#define NG    512
#define IMG   256
#define TW    16
#define TH    16
#define NT    256
#define NWARP (NT/32)

__device__ __forceinline__ float ex2(float x) {
    float y;
    asm("ex2.approx.ftz.f32 %0, %1;" : "=f"(y) : "f"(x));
    return y;
}

__global__ __launch_bounds__(NT)
void gs_fused(const float* __restrict__ pos,
              const float* __restrict__ cov3d,
              const float* __restrict__ opac,
              const float* __restrict__ cols,
              const float* __restrict__ Km,
              const float* __restrict__ Rm,
              const float* __restrict__ tv,
              float* __restrict__ out)
{
    __shared__ float4             rec[NG][3];    // 24 KB depth-ordered records
    __shared__ unsigned long long skey[NG];      // 4 KB
    __shared__ int                warpTotals[NWARP];  // popc0 | popc1<<16

    const int tid  = threadIdx.x;
    const int lane = tid & 31;
    const int wid  = tid >> 5;

    const int tileX = blockIdx.x * TW;
    const int tileY = blockIdx.y * TH;
    const float tX0 = (float)tileX, tX1 = (float)(tileX + TW);
    const float tY0 = (float)tileY, tY1 = (float)(tileY + TH);

    const float r00 = Rm[0], r01 = Rm[1], r02 = Rm[2];
    const float r10 = Rm[3], r11 = Rm[4], r12 = Rm[5];
    const float r20 = Rm[6], r21 = Rm[7], r22 = Rm[8];
    const float fx  = Km[0], fy = Km[4];

    // ---------------- phase 1: project 2 gaussians/thread ----------------
    bool  flg[2];
    unsigned long long key[2];
    float Fmx[2], Fmy[2], Fe00[2], Fe01[2], Fe11[2], Fbias[2];
    float Fcr[2], Fcg[2], Fcb[2];
    unsigned Flo[2], Fhi[2];

    #pragma unroll
    for (int s = 0; s < 2; s++) {
        const int g = tid + s * NT;
        const float p0 = pos[3*g+0], p1 = pos[3*g+1], p2 = pos[3*g+2];

        const float cam0 = r00*p0 + r01*p1 + r02*p2 + tv[0];
        const float cam1 = r10*p0 + r11*p1 + r12*p2 + tv[1];
        const float cam2 = r20*p0 + r21*p1 + r22*p2 + tv[2];

        const float pr0 = Km[0]*cam0 + Km[1]*cam1 + Km[2]*cam2;
        const float pr1 = Km[3]*cam0 + Km[4]*cam1 + Km[5]*cam2;
        const float pr2 = Km[6]*cam0 + Km[7]*cam1 + Km[8]*cam2;
        const float mx = pr0 / pr2;
        const float my = pr1 / pr2;

        const float z   = cam2;
        const float iz  = 1.0f / z;
        const float jx0 = fx * iz;
        const float jx2 = -fx * cam0 * iz * iz;
        const float jy1 = fy * iz;
        const float jy2 = -fy * cam1 * iz * iz;

        // P = J * R  (2x3)
        const float P00 = jx0*r00 + jx2*r20;
        const float P01 = jx0*r01 + jx2*r21;
        const float P02 = jx0*r02 + jx2*r22;
        const float P10 = jy1*r10 + jy2*r20;
        const float P11 = jy1*r11 + jy2*r21;
        const float P12 = jy1*r12 + jy2*r22;

        const float c00 = cov3d[9*g+0];
        const float c01 = cov3d[9*g+1];
        const float c02 = cov3d[9*g+2];
        const float c11 = cov3d[9*g+4];
        const float c12 = cov3d[9*g+5];
        const float c22 = cov3d[9*g+8];

        const float t00 = c00*P00 + c01*P01 + c02*P02;
        const float t01 = c01*P00 + c11*P01 + c12*P02;
        const float t02 = c02*P00 + c12*P01 + c22*P02;
        const float t10 = c00*P10 + c01*P11 + c02*P12;
        const float t11 = c01*P10 + c11*P11 + c12*P12;
        const float t12 = c02*P10 + c12*P11 + c22*P12;

        const float a = P00*t00 + P01*t01 + P02*t02 + 0.3f;
        const float b = P10*t00 + P11*t01 + P12*t02;
        const float c = P10*t10 + P11*t11 + P12*t12 + 0.3f;

        const float det  = fmaxf(a*c - b*b, 1e-8f);
        const float idet = 1.0f / det;
        // exp2 prescale: exp(-0.5*m) = exp2(-0.72134752*m)
        Fe00[s] = -0.72134752f * c * idet;
        Fe01[s] =  1.44269504f * b * idet;
        Fe11[s] = -0.72134752f * a * idet;

        const float hd = (a - c) * 0.5f;
        const float max_eig = (a + c)*0.5f + sqrtf(fmaxf(hd*hd + b*b, 1e-8f));
        const float radius = 3.0f * sqrtf(max_eig);

        const float x_min = fmaxf(0.0f,       truncf(mx - radius));
        const float x_max = fminf((float)IMG, truncf(mx + radius) + 1.0f);
        const float y_min = fmaxf(0.0f,       truncf(my - radius));
        const float y_max = fminf((float)IMG, truncf(my + radius) + 1.0f);

        flg[s] = (x_min < tX1) && (x_max > tX0) &&
                 (y_min < tY1) && (y_max > tY0);
        key[s] = ((unsigned long long)__float_as_uint(z) << 16)
               | (unsigned long long)g;

        Fmx[s] = mx;  Fmy[s] = my;
        Fbias[s] = __log2f(opac[g]);
        Fcr[s] = cols[3*g+0];  Fcg[s] = cols[3*g+1];  Fcb[s] = cols[3*g+2];
        Flo[s] = (unsigned)x_min | ((unsigned)x_max << 16);
        Fhi[s] = (unsigned)y_min | ((unsigned)y_max << 16);
    }

    // ---------------- phase 2: compaction slots ----------------
    const unsigned m0 = __ballot_sync(0xffffffffu, flg[0]);
    const unsigned m1 = __ballot_sync(0xffffffffu, flg[1]);
    if (lane == 0) warpTotals[wid] = __popc(m0) | (__popc(m1) << 16);
    __syncthreads();

    int prefix = 0, total = 0;
    #pragma unroll
    for (int w = 0; w < NWARP; w++) {
        const int t = warpTotals[w];
        if (w < wid) prefix += t;
        total += t;
    }
    const int count0 = total & 0xffff;
    const int count  = count0 + (total >> 16);
    const unsigned lm = (1u << lane) - 1u;
    const int pos0 = (prefix & 0xffff) + __popc(m0 & lm);
    const int pos1 = count0 + (prefix >> 16) + __popc(m1 & lm);

    if (flg[0]) skey[pos0] = key[0];
    if (flg[1]) skey[pos1] = key[1];
    __syncthreads();

    // ---------------- phase 3: rank + scatter ----------------
    if (flg[0] | flg[1]) {
        int rank0 = 0, rank1 = 0;
        for (int j = 0; j < count; j++) {
            const unsigned long long kj = skey[j];
            rank0 += (kj < key[0]);
            rank1 += (kj < key[1]);
        }
        if (flg[0]) {
            rec[rank0][0] = make_float4(Fmx[0], Fmy[0], Fe00[0], Fe01[0]);
            rec[rank0][1] = make_float4(Fe11[0], Fbias[0], Fcr[0], Fcg[0]);
            rec[rank0][2] = make_float4(Fcb[0], __uint_as_float(Flo[0]),
                                        __uint_as_float(Fhi[0]), 0.f);
        }
        if (flg[1]) {
            rec[rank1][0] = make_float4(Fmx[1], Fmy[1], Fe00[1], Fe01[1]);
            rec[rank1][1] = make_float4(Fe11[1], Fbias[1], Fcr[1], Fcg[1]);
            rec[rank1][2] = make_float4(Fcb[1], __uint_as_float(Flo[1]),
                                        __uint_as_float(Fhi[1]), 0.f);
        }
    }
    // pad to multiple of 4 with never-inside dummies
    const int countPad = (count + 3) & ~3;
    for (int t = count + tid; t < countPad; t += NT) {
        rec[t][0] = make_float4(0.f, 0.f, 0.f, 0.f);
        rec[t][1] = make_float4(0.f, 0.f, 0.f, 0.f);
        rec[t][2] = make_float4(0.f, __uint_as_float(0xFFFFu),
                                __uint_as_float(0xFFFFu), 0.f);
    }
    __syncthreads();

    // ---------------- phase 4: batched composite ----------------
    const int pxi = tileX + (tid & (TW - 1));
    const int pyi = tileY + (tid / TW);
    const float pxf = (float)pxi;
    const float pyf = (float)pyi;

    float T = 1.0f, rr = 0.0f, gg = 0.0f, bb = 0.0f;
    for (int base = 0; base < countPad; base += 4) {
        float4 q0[4], q1[4], q2[4];
        #pragma unroll
        for (int i = 0; i < 4; i++) {
            q0[i] = rec[base+i][0];
            q1[i] = rec[base+i][1];
            q2[i] = rec[base+i][2];
        }
        float gs[4];
        #pragma unroll
        for (int i = 0; i < 4; i++) {
            const unsigned lo = __float_as_uint(q2[i].y);
            const unsigned hi = __float_as_uint(q2[i].z);
            const int x0 = (int)(lo & 0xffffu), x1 = (int)(lo >> 16);
            const int y0 = (int)(hi & 0xffffu), y1 = (int)(hi >> 16);
            const bool inb = (pxi >= x0) & (pxi < x1) & (pyi >= y0) & (pyi < y1);
            const float dx = pxf - q0[i].x;
            const float dy = pyf - q0[i].y;
            // e = e00 dx^2 + e01 dx dy + e11 dy^2 + log2(op)
            const float qy = fmaf(q1[i].x, dy, 0.0f);           // e11*dy
            const float u  = fmaf(qy, dy, q1[i].y);             // e11*dy^2 + bias
            const float pl = fmaf(q0[i].w, dy, q0[i].z * dx);   // e01*dy + e00*dx
            const float e  = fmaf(pl, dx, u);
            gs[i] = inb ? ex2(e) : 0.0f;                        // = alpha
        }
        #pragma unroll
        for (int i = 0; i < 4; i++) {
            const float tg = T * gs[i];
            rr = fmaf(tg, q1[i].z, rr);
            gg = fmaf(tg, q1[i].w, gg);
            bb = fmaf(tg, q2[i].x, bb);
            T  = T - tg;
        }
        if (T < 1e-5f) break;
    }

    const int idx = (pyi * IMG + pxi) * 3;
    out[idx + 0] = rr;
    out[idx + 1] = gg;
    out[idx + 2] = bb;
}

extern "C" void kernel_launch(void* const* d_in, const int* in_sizes, int n_in,
                              void* d_out, int out_size)
{
    const float* pos   = (const float*)d_in[0];  // (512,3)
    const float* cov3d = (const float*)d_in[1];  // (512,3,3)
    const float* opac  = (const float*)d_in[2];  // (512,1)
    const float* cols  = (const float*)d_in[3];  // (512,3)
    const float* Km    = (const float*)d_in[4];  // (3,3)
    const float* Rm    = (const float*)d_in[5];  // (3,3)
    const float* tv    = (const float*)d_in[6];  // (3,)
    float* out = (float*)d_out;                  // (256,256,3)

    gs_fused<<<dim3(IMG/TW, IMG/TH), NT>>>(pos, cov3d, opac, cols, Km, Rm, tv, out);
}